// round 2
// baseline (speedup 1.0000x reference)
#include <cuda_runtime.h>

#define N_  64
#define C_  128
#define T_  2048
#define S_  9
#define TT  128
#define NTILES (T_ / TT)     // 16
#define NBLK   (N_ * NTILES) // 1024
#define EPS_ 1e-5f

// Deterministic per-block partial sums (no atomics)
__device__ float g_part_sum[C_][NBLK];
__device__ float g_part_sq [C_][NBLK];
__device__ float g_scale[C_];
__device__ float g_bias [C_];

// Dynamic smem layout (floats):
//   sm_x   : 136 * 128          (shifted x tile with 4-row zero halo top+bottom)
//   sw     : 128 * 12           (weights padded to 12/row for float4 loads)
//   red_sum: 128 * 33           (stats kernel only; +1 pad vs bank conflicts)
//   red_sq : 128 * 33
#define SMX_FLOATS (136 * 128)
#define SW_FLOATS  (128 * 12)
#define RED_FLOATS (128 * 33)

template<int WRITE>
__global__ void __launch_bounds__(256)
conv_kernel(const float* __restrict__ x,
            const float* __restrict__ cw,
            float* __restrict__ out)
{
    extern __shared__ float smem[];
    float* sm_x    = smem;
    float* sw      = smem + SMX_FLOATS;
    float* red_sum = sw + SW_FLOATS;
    float* red_sq  = red_sum + RED_FLOATS;

    const int tid = threadIdx.x;
    const int bx  = blockIdx.x;      // time tile
    const int n   = blockIdx.y;      // batch
    const int t0  = bx * TT;

    // ---- Phase A: stage weights, zero channel halo, load shifted x tile ----
    for (int idx = tid; idx < C_ * S_; idx += 256) {
        int c = idx / 9, s = idx - c * 9;
        sw[c * 12 + s] = cw[idx];
    }
    for (int idx = tid; idx < 8 * 128; idx += 256) {
        int r = idx >> 7;
        int row = (r < 4) ? r : (r + 128);   // rows 0..3 and 132..135
        sm_x[row * 128 + (idx & 127)] = 0.f;
    }
    const float* xn = x + (size_t)n * C_ * T_;
    #pragma unroll 4
    for (int idx = tid; idx < C_ * TT; idx += 256) {
        int cc = idx >> 7;           // channel
        int tt = idx & 127;
        int sh = (cc % 9) - 4;       // per-channel time shift
        int tsrc = t0 + tt - sh;
        float v = 0.f;
        if (tsrc >= 0 && tsrc < T_) v = xn[cc * T_ + tsrc];
        sm_x[(cc + 4) * 128 + tt] = v;   // row = channel + 4 (halo offset)
    }
    __syncthreads();

    // ---- Phase B: banded conv with 9-row register sliding window ----
    // warp w owns output channels [16w, 16w+16); out[c] reads sm rows c..c+8.
    // lane handles float2 columns (lane) and (lane+32) -> tt {2l,2l+1, 64+2l, 64+2l+1}.
    const int warp = tid >> 5;
    const int lane = tid & 31;
    const int c0   = warp * 16;

    float2 p0[9], p1[9];
    #pragma unroll
    for (int j = 0; j < 8; ++j) {
        const float2* rp = (const float2*)(sm_x + (c0 + j) * 128);
        p0[j] = rp[lane];
        p1[j] = rp[lane + 32];
    }
    #pragma unroll
    for (int i = 0; i < 16; ++i) {
        {   // slide: bring in row c0+i+8
            const int slot = (i + 8) % 9;
            const float2* rp = (const float2*)(sm_x + (c0 + i + 8) * 128);
            p0[slot] = rp[lane];
            p1[slot] = rp[lane + 32];
        }
        const int c = c0 + i;
        const float* wr = sw + c * 12;
        const float4 wA = *(const float4*)wr;
        const float4 wB = *(const float4*)(wr + 4);
        const float  w8v = wr[8];

        float a0 = 0.f, a1 = 0.f, a2 = 0.f, a3 = 0.f;
        #define ACC1(s, ws) { const int sl = (i + (s)) % 9;            \
            a0 = fmaf((ws), p0[sl].x, a0); a1 = fmaf((ws), p0[sl].y, a1); \
            a2 = fmaf((ws), p1[sl].x, a2); a3 = fmaf((ws), p1[sl].y, a3); }
        ACC1(0, wA.x) ACC1(1, wA.y) ACC1(2, wA.z) ACC1(3, wA.w)
        ACC1(4, wB.x) ACC1(5, wB.y) ACC1(6, wB.z) ACC1(7, wB.w)
        ACC1(8, w8v)
        #undef ACC1

        if (WRITE) {
            const float sc = g_scale[c];
            const float bi = g_bias[c];
            float2 r0, r1;
            r0.x = fmaxf(fmaf(a0, sc, bi), 0.f);
            r0.y = fmaxf(fmaf(a1, sc, bi), 0.f);
            r1.x = fmaxf(fmaf(a2, sc, bi), 0.f);
            r1.y = fmaxf(fmaf(a3, sc, bi), 0.f);
            float2* op = (float2*)(out + (size_t)(n * C_ + c) * T_ + t0);
            op[lane]      = r0;
            op[lane + 32] = r1;
        } else {
            red_sum[c * 33 + lane] = a0 + a1 + a2 + a3;
            red_sq [c * 33 + lane] = fmaf(a0, a0, fmaf(a1, a1, fmaf(a2, a2, a3 * a3)));
        }
    }

    // ---- Phase C (stats pass only): per-block per-channel partials ----
    if (!WRITE) {
        __syncthreads();
        if (tid < 128) {
            float s = 0.f, q = 0.f;
            #pragma unroll
            for (int j = 0; j < 32; ++j) {
                s += red_sum[tid * 33 + j];
                q += red_sq [tid * 33 + j];
            }
            const int bid = n * NTILES + bx;
            g_part_sum[tid][bid] = s;
            g_part_sq [tid][bid] = q;
        }
    }
}

__global__ void __launch_bounds__(256)
finalize_kernel(const float* __restrict__ gamma, const float* __restrict__ beta)
{
    __shared__ float rs[256], rq[256];
    const int c = blockIdx.x;
    const int tid = threadIdx.x;
    float s = 0.f, q = 0.f;
    #pragma unroll
    for (int j = tid; j < NBLK; j += 256) {
        s += g_part_sum[c][j];
        q += g_part_sq [c][j];
    }
    rs[tid] = s; rq[tid] = q;
    __syncthreads();
    #pragma unroll
    for (int off = 128; off > 0; off >>= 1) {
        if (tid < off) { rs[tid] += rs[tid + off]; rq[tid] += rq[tid + off]; }
        __syncthreads();
    }
    if (tid == 0) {
        const float invNT = 1.f / (float)(N_ * T_);
        const float m   = rs[0] * invNT;
        const float v   = rq[0] * invNT - m * m;
        const float inv = rsqrtf(v + EPS_);
        const float sc  = gamma[c] * inv;
        g_scale[c] = sc;
        g_bias [c] = beta[c] - m * sc;
    }
}

extern "C" void kernel_launch(void* const* d_in, const int* in_sizes, int n_in,
                              void* d_out, int out_size)
{
    const float* x     = (const float*)d_in[0];
    const float* cw    = (const float*)d_in[1];
    const float* gamma = (const float*)d_in[2];
    const float* beta  = (const float*)d_in[3];
    float* out = (float*)d_out;

    const size_t smem_stats = (size_t)(SMX_FLOATS + SW_FLOATS + 2 * RED_FLOATS) * sizeof(float); // 109568
    const size_t smem_write = (size_t)(SMX_FLOATS + SW_FLOATS) * sizeof(float);                  // 75776

    cudaFuncSetAttribute(conv_kernel<0>, cudaFuncAttributeMaxDynamicSharedMemorySize, (int)smem_stats);
    cudaFuncSetAttribute(conv_kernel<1>, cudaFuncAttributeMaxDynamicSharedMemorySize, (int)smem_write);

    dim3 grid(NTILES, N_);
    conv_kernel<0><<<grid, 256, smem_stats>>>(x, cw, nullptr);
    finalize_kernel<<<C_, 256>>>(gamma, beta);
    conv_kernel<1><<<grid, 256, smem_write>>>(x, cw, out);
}

// round 4
// speedup vs baseline: 1.1145x; 1.1145x over previous
#include <cuda_runtime.h>

#define N_   64
#define C_   128
#define T_   2048
#define EPS_ 1e-5f

// Per-half warps: 4 tchunks * 64 n * 4 warps = 1024; keep 8 partial lanes each.
#define NWARPS 1024
#define PARTW  8
#define NPART  (NWARPS * PARTW)   // 8192

__device__ float g_ps[C_][NPART];
__device__ float g_pq[C_][NPART];
__device__ float g_scale[C_];
__device__ float g_bias [C_];

// Channel sweep: thread owns 4 time columns (t0, t0+128, t0+256, t0+384).
// y[c'] = x[c', t - sh(c')], sh(c') = c'%9 - 4.  out[c] = sum_s w[c,s]*y[c-4+s].
// Ring of 9 y-values per column; all ring indices / shifts are compile-time.
template<int CLO, int WRITE, int SAFE>
__device__ __forceinline__ void sweep(
    const float* __restrict__ xn, float* __restrict__ outn,
    const float* __restrict__ sw, const float* __restrict__ ssc,
    const float* __restrict__ sbi, int t0, int bid8, int lane)
{
    const float* xt = xn + t0;
    float* ot = outn + t0;   // only dereferenced when WRITE

    float y0[9], y1[9], y2[9], y3[9];
    #pragma unroll
    for (int k = 0; k < 9; ++k) { y0[k]=0.f; y1[k]=0.f; y2[k]=0.f; y3[k]=0.f; }

    #pragma unroll
    for (int jj = 0; jj < 72; ++jj) {
        const int jg = CLO - 4 + jj;           // source channel being loaded
        if (jg >= 0 && jg < C_) {              // static after unroll
            const int m    = ((jg % 9) + 9) % 9;
            const int sh   = m - 4;
            const int off  = jg * T_ - sh;     // immediate offset
            if (SAFE) {
                y0[m] = xt[off];
                y1[m] = xt[off + 128];
                y2[m] = xt[off + 256];
                y3[m] = xt[off + 384];
            } else {
                int i = t0 - sh;
                y0[m] = ((unsigned)i < T_) ? xt[off]       : 0.f; i += 128;
                y1[m] = ((unsigned)i < T_) ? xt[off + 128] : 0.f; i += 128;
                y2[m] = ((unsigned)i < T_) ? xt[off + 256] : 0.f; i += 128;
                y3[m] = ((unsigned)i < T_) ? xt[off + 384] : 0.f;
            }
        } else if (jg >= C_) {
            // Top channel pad: ring slot would otherwise hold stale channel
            // jg-9 data. Must be explicit zero (bottom pad is covered by init).
            const int m = jg % 9;
            y0[m] = 0.f; y1[m] = 0.f; y2[m] = 0.f; y3[m] = 0.f;
        }
        if (jj >= 8) {                          // output channel c = CLO + jj - 8
            const int r = jj - 8;               // local row [0,64)
            const int c = CLO + r;
            const float4 wA = *(const float4*)(sw + r * 12);
            const float4 wB = *(const float4*)(sw + r * 12 + 4);
            const float  w8 = sw[r * 12 + 8];
            const int sb = (((jg - 8) % 9) + 9) % 9;   // slot of y[c-4]
            float a0 = 0.f, a1 = 0.f, a2 = 0.f, a3 = 0.f;
            #define TAP(s, ws) { const int sl = (sb + (s)) % 9;            \
                a0 = fmaf((ws), y0[sl], a0); a1 = fmaf((ws), y1[sl], a1);  \
                a2 = fmaf((ws), y2[sl], a2); a3 = fmaf((ws), y3[sl], a3); }
            TAP(0, wA.x) TAP(1, wA.y) TAP(2, wA.z) TAP(3, wA.w)
            TAP(4, wB.x) TAP(5, wB.y) TAP(6, wB.z) TAP(7, wB.w)
            TAP(8, w8)
            #undef TAP

            if (WRITE) {
                const float sc = ssc[r];
                const float bi = sbi[r];
                ot[c * T_      ] = fmaxf(fmaf(a0, sc, bi), 0.f);
                ot[c * T_ + 128] = fmaxf(fmaf(a1, sc, bi), 0.f);
                ot[c * T_ + 256] = fmaxf(fmaf(a2, sc, bi), 0.f);
                ot[c * T_ + 384] = fmaxf(fmaf(a3, sc, bi), 0.f);
            } else {
                float s = (a0 + a1) + (a2 + a3);
                float q = fmaf(a0, a0, fmaf(a1, a1, fmaf(a2, a2, a3 * a3)));
                // 2-stage butterfly: lane l holds sum over lanes == l (mod 8)
                s += __shfl_xor_sync(0xffffffffu, s, 16);
                q += __shfl_xor_sync(0xffffffffu, q, 16);
                s += __shfl_xor_sync(0xffffffffu, s, 8);
                q += __shfl_xor_sync(0xffffffffu, q, 8);
                if (lane < PARTW) {
                    g_ps[c][bid8 + lane] = s;
                    g_pq[c][bid8 + lane] = q;
                }
            }
        }
    }
}

template<int WRITE>
__global__ void __launch_bounds__(128)
conv_kernel(const float* __restrict__ x, const float* __restrict__ cw,
            float* __restrict__ out)
{
    __shared__ float sw[64 * 12];
    __shared__ float ssc[64], sbi[64];

    const int tid    = threadIdx.x;
    const int tchunk = blockIdx.x;     // 0..3 (512 t each)
    const int n      = blockIdx.y;     // 0..63
    const int half   = blockIdx.z;     // 0..1
    const int clo    = half * 64;

    for (int i = tid; i < 64 * 9; i += 128) {
        int r = i / 9, s = i - r * 9;
        sw[r * 12 + s] = cw[(clo + r) * 9 + s];
    }
    if (WRITE && tid < 64) {
        ssc[tid] = g_scale[clo + tid];
        sbi[tid] = g_bias [clo + tid];
    }
    __syncthreads();

    const int t0   = tchunk * 512 + tid;
    const int warp = tid >> 5, lane = tid & 31;
    const int tw   = tchunk * 512 + warp * 32;
    // All loads in range iff t-4 >= 0 and t+4 <= T-1 for every t in the warp.
    const bool safe = (tw >= 4) && (tw + 31 + 384 + 4 <= T_ - 1);
    const int bid8 = (((n * 4 + tchunk) * 4 + warp) * PARTW);

    const float* xn   = x   + (size_t)n * C_ * T_;
    float*       outn = out + (size_t)n * C_ * T_;

    if (half == 0) {
        if (safe) sweep<0, WRITE, 1>(xn, outn, sw, ssc, sbi, t0, bid8, lane);
        else      sweep<0, WRITE, 0>(xn, outn, sw, ssc, sbi, t0, bid8, lane);
    } else {
        if (safe) sweep<64, WRITE, 1>(xn, outn, sw, ssc, sbi, t0, bid8, lane);
        else      sweep<64, WRITE, 0>(xn, outn, sw, ssc, sbi, t0, bid8, lane);
    }
}

__global__ void __launch_bounds__(256)
finalize_kernel(const float* __restrict__ gamma, const float* __restrict__ beta)
{
    __shared__ float rs[256], rq[256];
    const int c = blockIdx.x;
    const int tid = threadIdx.x;
    float s = 0.f, q = 0.f;
    #pragma unroll 4
    for (int j = tid; j < NPART; j += 256) {
        s += g_ps[c][j];
        q += g_pq[c][j];
    }
    rs[tid] = s; rq[tid] = q;
    __syncthreads();
    #pragma unroll
    for (int off = 128; off > 0; off >>= 1) {
        if (tid < off) { rs[tid] += rs[tid + off]; rq[tid] += rq[tid + off]; }
        __syncthreads();
    }
    if (tid == 0) {
        const float invNT = 1.f / (float)(N_ * T_);
        const float m   = rs[0] * invNT;
        const float v   = rq[0] * invNT - m * m;
        const float inv = rsqrtf(v + EPS_);
        const float sc  = gamma[c] * inv;
        g_scale[c] = sc;
        g_bias [c] = beta[c] - m * sc;
    }
}

extern "C" void kernel_launch(void* const* d_in, const int* in_sizes, int n_in,
                              void* d_out, int out_size)
{
    const float* x     = (const float*)d_in[0];
    const float* cw    = (const float*)d_in[1];
    const float* gamma = (const float*)d_in[2];
    const float* beta  = (const float*)d_in[3];
    float* out = (float*)d_out;

    dim3 grid(4, N_, 2);
    conv_kernel<0><<<grid, 128>>>(x, cw, nullptr);
    finalize_kernel<<<C_, 256>>>(gamma, beta);
    conv_kernel<1><<<grid, 128>>>(x, cw, out);
}

// round 5
// speedup vs baseline: 1.4909x; 1.3377x over previous
#include <cuda_runtime.h>

#define N_   64
#define C_   128
#define T_   2048
#define EPS_ 1e-5f

// warps per half: 8 tchunks * 64 n * 4 warps = 2048; 8 partial lanes each.
#define NWARPS 2048
#define PARTW  8
#define NPART  (NWARPS * PARTW)   // 16384

__device__ float g_ps[C_][NPART];
__device__ float g_pq[C_][NPART];
__device__ float g_scale[C_];
__device__ float g_bias [C_];

// Channel sweep: thread owns 2 time columns (t0, t0+128).
// y[c'] = x[c', t - sh(c')], sh(c') = c'%9 - 4.  out[c] = sum_s w[c,s]*y[c-4+s].
// Ring of 9 y-values per column; all ring indices / shifts are compile-time.
template<int CLO, int WRITE, int SAFE>
__device__ __forceinline__ void sweep(
    const float* __restrict__ xn, float* __restrict__ outn,
    const float* __restrict__ sw, const float* __restrict__ ssc,
    const float* __restrict__ sbi, int t0, int bid8, int lane)
{
    const float* xt = xn + t0;
    float* ot = outn + t0;   // only dereferenced when WRITE

    float y0[9], y1[9];
    #pragma unroll
    for (int k = 0; k < 9; ++k) { y0[k] = 0.f; y1[k] = 0.f; }

    #pragma unroll
    for (int jj = 0; jj < 72; ++jj) {
        const int jg = CLO - 4 + jj;           // source channel being loaded
        if (jg >= 0 && jg < C_) {              // static after unroll
            const int m    = ((jg % 9) + 9) % 9;
            const int sh   = m - 4;
            const int off  = jg * T_ - sh;     // immediate offset
            if (SAFE) {
                y0[m] = xt[off];
                y1[m] = xt[off + 128];
            } else {
                int i = t0 - sh;
                y0[m] = ((unsigned)i < T_) ? xt[off]       : 0.f; i += 128;
                y1[m] = ((unsigned)i < T_) ? xt[off + 128] : 0.f;
            }
        } else if (jg >= C_) {
            // Top channel pad: slot would otherwise hold stale channel jg-9.
            const int m = jg % 9;
            y0[m] = 0.f; y1[m] = 0.f;
        }
        if (jj >= 8) {                          // output channel c = CLO + jj - 8
            const int r = jj - 8;               // local row [0,64)
            const int c = CLO + r;
            const float4 wA = *(const float4*)(sw + r * 12);
            const float4 wB = *(const float4*)(sw + r * 12 + 4);
            const float  w8 = sw[r * 12 + 8];
            const int sb = (((jg - 8) % 9) + 9) % 9;   // slot of y[c-4]
            float a0 = 0.f, a1 = 0.f;
            #define TAP(s, ws) { const int sl = (sb + (s)) % 9;            \
                a0 = fmaf((ws), y0[sl], a0); a1 = fmaf((ws), y1[sl], a1); }
            TAP(0, wA.x) TAP(1, wA.y) TAP(2, wA.z) TAP(3, wA.w)
            TAP(4, wB.x) TAP(5, wB.y) TAP(6, wB.z) TAP(7, wB.w)
            TAP(8, w8)
            #undef TAP

            if (WRITE) {
                const float sc = ssc[r];
                const float bi = sbi[r];
                ot[c * T_      ] = fmaxf(fmaf(a0, sc, bi), 0.f);
                ot[c * T_ + 128] = fmaxf(fmaf(a1, sc, bi), 0.f);
            } else {
                float s = a0 + a1;
                float q = fmaf(a0, a0, a1 * a1);
                // 2-stage butterfly: lane l holds sum over lanes == l (mod 8)
                s += __shfl_xor_sync(0xffffffffu, s, 16);
                q += __shfl_xor_sync(0xffffffffu, q, 16);
                s += __shfl_xor_sync(0xffffffffu, s, 8);
                q += __shfl_xor_sync(0xffffffffu, q, 8);
                if (lane < PARTW) {
                    g_ps[c][bid8 + lane] = s;
                    g_pq[c][bid8 + lane] = q;
                }
            }
        }
    }
}

template<int WRITE>
__global__ void __launch_bounds__(128, 8)
conv_kernel(const float* __restrict__ x, const float* __restrict__ cw,
            float* __restrict__ out)
{
    __shared__ float sw[64 * 12];
    __shared__ float ssc[64], sbi[64];

    const int tid    = threadIdx.x;
    const int tchunk = blockIdx.x;     // 0..7 (256 t each)
    const int n      = blockIdx.y;     // 0..63
    const int half   = blockIdx.z;     // 0..1
    const int clo    = half * 64;

    for (int i = tid; i < 64 * 9; i += 128) {
        int r = i / 9, s = i - r * 9;
        sw[r * 12 + s] = cw[(clo + r) * 9 + s];
    }
    if (WRITE && tid < 64) {
        ssc[tid] = g_scale[clo + tid];
        sbi[tid] = g_bias [clo + tid];
    }
    __syncthreads();

    const int t0   = tchunk * 256 + tid;
    const int warp = tid >> 5, lane = tid & 31;
    const int tw   = tchunk * 256 + warp * 32;
    // All loads in range iff tw-4 >= 0 and tw+31+128+4 <= T-1.
    const bool safe = (tw >= 4) && (tw + 31 + 128 + 4 <= T_ - 1);
    const int bid8 = (((n * 8 + tchunk) * 4 + warp) * PARTW);

    const float* xn   = x   + (size_t)n * C_ * T_;
    float*       outn = out + (size_t)n * C_ * T_;

    if (half == 0) {
        if (safe) sweep<0, WRITE, 1>(xn, outn, sw, ssc, sbi, t0, bid8, lane);
        else      sweep<0, WRITE, 0>(xn, outn, sw, ssc, sbi, t0, bid8, lane);
    } else {
        if (safe) sweep<64, WRITE, 1>(xn, outn, sw, ssc, sbi, t0, bid8, lane);
        else      sweep<64, WRITE, 0>(xn, outn, sw, ssc, sbi, t0, bid8, lane);
    }
}

__global__ void __launch_bounds__(256)
finalize_kernel(const float* __restrict__ gamma, const float* __restrict__ beta)
{
    __shared__ float rs[256], rq[256];
    const int c = blockIdx.x;
    const int tid = threadIdx.x;
    float s = 0.f, q = 0.f;
    #pragma unroll 8
    for (int j = tid; j < NPART; j += 256) {
        s += g_ps[c][j];
        q += g_pq[c][j];
    }
    rs[tid] = s; rq[tid] = q;
    __syncthreads();
    #pragma unroll
    for (int off = 128; off > 0; off >>= 1) {
        if (tid < off) { rs[tid] += rs[tid + off]; rq[tid] += rq[tid + off]; }
        __syncthreads();
    }
    if (tid == 0) {
        const float invNT = 1.f / (float)(N_ * T_);
        const float m   = rs[0] * invNT;
        const float v   = rq[0] * invNT - m * m;
        const float inv = rsqrtf(v + EPS_);
        const float sc  = gamma[c] * inv;
        g_scale[c] = sc;
        g_bias [c] = beta[c] - m * sc;
    }
}

extern "C" void kernel_launch(void* const* d_in, const int* in_sizes, int n_in,
                              void* d_out, int out_size)
{
    const float* x     = (const float*)d_in[0];
    const float* cw    = (const float*)d_in[1];
    const float* gamma = (const float*)d_in[2];
    const float* beta  = (const float*)d_in[3];
    float* out = (float*)d_out;

    dim3 grid(8, N_, 2);
    conv_kernel<0><<<grid, 128>>>(x, cw, nullptr);
    finalize_kernel<<<C_, 256>>>(gamma, beta);
    conv_kernel<1><<<grid, 128>>>(x, cw, out);
}